// round 17
// baseline (speedup 1.0000x reference)
#include <cuda_runtime.h>
#include <cuda_fp16.h>

// Problem constants
#define BATCH 32
#define CH    512
#define NPIX  1024   // H*W = 32*32
#define NGRP  32
#define CPG   16     // channels per group

// ---------------------------------------------------------------------------
// Scratch (device globals — no allocations allowed)
// ---------------------------------------------------------------------------
__device__ __half g_wq   [(size_t)3 * CH * CH];                 // qkv_w
__device__ __half g_wp   [(size_t)CH * CH];                     // proj_w
__device__ __half g_hb   [(size_t)BATCH * CH * NPIX];           // groupnorm out
__device__ __half g_qkvb [(size_t)BATCH * 3 * CH * NPIX];       // qkv out
__device__ __half g_attb [(size_t)BATCH * NPIX * NPIX];         // softmax out
__device__ __half g_houtb[(size_t)BATCH * CH * NPIX];           // attn*V out
__device__ float g_attn[(size_t)BATCH * NPIX * NPIX];           // scores (fp32)

// ---------------------------------------------------------------------------
// Helpers
// ---------------------------------------------------------------------------
__device__ __forceinline__ float warp_sum(float v) {
    #pragma unroll
    for (int o = 16; o; o >>= 1) v += __shfl_xor_sync(0xffffffffu, v, o);
    return v;
}
__device__ __forceinline__ float warp_max(float v) {
    #pragma unroll
    for (int o = 16; o; o >>= 1) v = fmaxf(v, __shfl_xor_sync(0xffffffffu, v, o));
    return v;
}

__device__ __forceinline__ void mma_f16(float* d, const unsigned* a, const unsigned* b) {
    asm volatile(
        "mma.sync.aligned.m16n8k16.row.col.f32.f16.f16.f32 "
        "{%0,%1,%2,%3}, {%4,%5,%6,%7}, {%8,%9}, {%0,%1,%2,%3};"
        : "+f"(d[0]), "+f"(d[1]), "+f"(d[2]), "+f"(d[3])
        : "r"(a[0]), "r"(a[1]), "r"(a[2]), "r"(a[3]),
          "r"(b[0]), "r"(b[1]));
}

template<bool T>
__device__ __forceinline__ void ldsm4(unsigned r[4], unsigned addr) {
    if (T)
        asm volatile("ldmatrix.sync.aligned.m8n8.x4.trans.shared.b16 {%0,%1,%2,%3}, [%4];"
                     : "=r"(r[0]), "=r"(r[1]), "=r"(r[2]), "=r"(r[3]) : "r"(addr));
    else
        asm volatile("ldmatrix.sync.aligned.m8n8.x4.shared.b16 {%0,%1,%2,%3}, [%4];"
                     : "=r"(r[0]), "=r"(r[1]), "=r"(r[2]), "=r"(r[3]) : "r"(addr));
}

__device__ __forceinline__ void cp16(unsigned dst, const void* src) {
    asm volatile("cp.async.cg.shared.global [%0], [%1], 16;" :: "r"(dst), "l"(src));
}
__device__ __forceinline__ void cp_commit() { asm volatile("cp.async.commit_group;"); }

// ---------------------------------------------------------------------------
// Weight round kernel (fp32 -> fp16)
// ---------------------------------------------------------------------------
__global__ void wround_k(const float* __restrict__ src, __half* __restrict__ dst) {
    const int i4 = blockIdx.x * 256 + threadIdx.x;
    float4 v = ((const float4*)src)[i4];
    ((__half2*)dst)[i4*2+0] = __floats2half2_rn(v.x, v.y);
    ((__half2*)dst)[i4*2+1] = __floats2half2_rn(v.z, v.w);
}

// ---------------------------------------------------------------------------
// Fused GroupNorm: one block per (batch, group). Slab = 16 ch * 1024 pix.
// ---------------------------------------------------------------------------
__global__ void gn_fused_k(const float* __restrict__ x,
                           const float* __restrict__ w,
                           const float* __restrict__ b) {
    const int bg = blockIdx.x;                       // b*32 + g
    const float4* p = (const float4*)(x + (size_t)bg * (CPG * NPIX));
    float s = 0.f, ss = 0.f;
    #pragma unroll 4
    for (int i = threadIdx.x; i < (CPG * NPIX) / 4; i += 256) {
        float4 v = p[i];
        s  += v.x + v.y + v.z + v.w;
        ss += v.x * v.x + v.y * v.y + v.z * v.z + v.w * v.w;
    }
    __shared__ float sh1[8], sh2[8];
    __shared__ float s_mean, s_rstd;
    s = warp_sum(s); ss = warp_sum(ss);
    const int wi = threadIdx.x >> 5, l = threadIdx.x & 31;
    if (!l) { sh1[wi] = s; sh2[wi] = ss; }
    __syncthreads();
    if (threadIdx.x < 32) {
        float a = (threadIdx.x < 8) ? sh1[threadIdx.x] : 0.f;
        float c = (threadIdx.x < 8) ? sh2[threadIdx.x] : 0.f;
        a = warp_sum(a); c = warp_sum(c);
        if (!threadIdx.x) {
            const float inv_n = 1.f / (float)(CPG * NPIX);
            float m   = a * inv_n;
            float var = c * inv_n - m * m;
            s_mean = m;
            s_rstd = rsqrtf(var + 1e-5f);
        }
    }
    __syncthreads();
    const float m = s_mean, r = s_rstd;
    const int g16 = (bg & (NGRP - 1)) * CPG;         // first channel of group
    __half2* dst = (__half2*)(g_hb + (size_t)bg * (CPG * NPIX));
    #pragma unroll 4
    for (int i = threadIdx.x; i < (CPG * NPIX) / 4; i += 256) {
        const int c = g16 + (i >> 8);                // 256 f4 per channel
        const float sc = r * w[c];
        const float sh = b[c] - m * sc;
        float4 v = p[i];
        dst[i*2+0] = __floats2half2_rn(v.x*sc+sh, v.y*sc+sh);
        dst[i*2+1] = __floats2half2_rn(v.z*sc+sh, v.w*sc+sh);
    }
}

// ---------------------------------------------------------------------------
// Batched fp16 tensor-core GEMM, 4-stage cp.async pipeline, ldmatrix x4.
//   logical C[m][n] = alpha * sum_k A(m,k)*B(k,n)
//   A_T: A source stored [K][M] (ld=lda), smem [k][m], ldmatrix.trans
//   B_T: B source stored [K][N] (ld=ldb), smem [k][n], ldmatrix.trans
//   OUTM: 0 = fp32*alpha | 1 = fp32 + bias[row] + res
//         2 = fp16 + bias[row] | 3 = fp16
// CTA tile 128x128x32, 256 threads (2x4 warps), warp tile 64x32, m16n8k16.
// 16 warps/SM target (regs <= 128). All dims multiples of tile sizes. K/32>=4.
// ---------------------------------------------------------------------------
template<bool A_T, bool B_T, int OUTM>
__global__ void __launch_bounds__(256, 2) gemm_h(
    const __half* __restrict__ A, const __half* __restrict__ B,
    float* __restrict__ C, __half* __restrict__ Ch,
    const float* __restrict__ bias, const float* __restrict__ res,
    int M, int N, int K, int lda, int ldb,
    size_t sA, size_t sB, size_t sC, float alpha)
{
    // per-tile smem bytes (row-pitch padded: 40 h / 136 h)
    constexpr int A_PB  = (A_T ? 32 * 136 : 128 * 40) * 2;
    constexpr int B_PB  = (B_T ? 32 * 136 : 128 * 40) * 2;
    constexpr int STAGE = A_PB + B_PB;

    extern __shared__ char smem[];
    const unsigned sbase = (unsigned)__cvta_generic_to_shared(smem);

    const int bz = blockIdx.z;
    A += sA * bz; B += sB * bz;
    if (OUTM == 0 || OUTM == 1) { C += sC * bz; if (OUTM == 1) res += sC * bz; }
    else Ch += sC * bz;

    const int tid = threadIdx.x;
    const int m0 = blockIdx.y * 128, n0 = blockIdx.x * 128;
    const int wid = tid >> 5, lane = tid & 31;
    const int wm = (wid >> 2) * 64;     // warp rows: 0 / 64
    const int wn = (wid & 3) * 32;      // warp cols: 0 / 32 / 64 / 96
    const int gid = lane >> 2, tid4 = lane & 3;

    float acc[4][4][4];
    #pragma unroll
    for (int mi = 0; mi < 4; mi++)
        #pragma unroll
        for (int ni = 0; ni < 4; ni++)
            #pragma unroll
            for (int j = 0; j < 4; j++) acc[mi][ni][j] = 0.f;

    // ---- async stage loader: A 512 chunks + B 512 chunks, 256 threads ----
    auto load_stage = [&](int st, int kt) {
        const unsigned base = sbase + st * STAGE;
        #pragma unroll
        for (int c = tid; c < 512; c += 256) {
            if (A_T) {
                const int row = c >> 4, seg = c & 15;
                cp16(base + row * 272 + seg * 16,
                     A + (size_t)(kt + row) * lda + m0 + seg * 8);
            } else {
                const int row = c >> 2, seg = c & 3;
                cp16(base + row * 80 + seg * 16,
                     A + (size_t)(m0 + row) * lda + kt + seg * 8);
            }
        }
        #pragma unroll
        for (int c = tid; c < 512; c += 256) {
            if (B_T) {
                const int row = c >> 4, seg = c & 15;
                cp16(base + A_PB + row * 272 + seg * 16,
                     B + (size_t)(kt + row) * ldb + n0 + seg * 8);
            } else {
                const int row = c >> 2, seg = c & 3;
                cp16(base + A_PB + row * 80 + seg * 16,
                     B + (size_t)(n0 + row) * ldb + kt + seg * 8);
            }
        }
    };

    const int la15 = lane & 15, la7 = lane & 7;
    const int la_hi4 = lane >> 4, la_b3 = (lane >> 3) & 1;

    const int T = K / 32;   // >= 4 for all our shapes
    load_stage(0, 0);  cp_commit();
    load_stage(1, 32); cp_commit();
    load_stage(2, 64); cp_commit();

    for (int t = 0; t < T; t++) {
        asm volatile("cp.async.wait_group 2;");   // stage t complete
        __syncthreads();                          // fences reuse of slot (t+3)&3
        if (t + 3 < T) load_stage((t + 3) & 3, (t + 3) * 32);
        cp_commit();                              // uniform group accounting

        const unsigned aBase = sbase + (t & 3) * STAGE;
        const unsigned bBase = aBase + A_PB;

        #pragma unroll
        for (int ks = 0; ks < 32; ks += 16) {
            // B fragments: 4 n-frags of 8 cols via 2 ldsm4
            unsigned bh[4][2];
            #pragma unroll
            for (int nip = 0; nip < 2; nip++) {
                const int nf = wn + nip * 16;
                unsigned off;
                if (B_T) {
                    off = bBase + (ks + la7 + 8 * la_b3) * 272 + (nf + 8 * la_hi4) * 2;
                } else {
                    off = bBase + (nf + la7 + 8 * la_hi4) * 80 + (ks + 8 * la_b3) * 2;
                }
                unsigned r[4];
                ldsm4<B_T>(r, off);
                bh[nip*2][0] = r[0]; bh[nip*2][1] = r[1];
                bh[nip*2+1][0] = r[2]; bh[nip*2+1][1] = r[3];
            }
            #pragma unroll
            for (int mi = 0; mi < 4; mi++) {
                const int mf = wm + mi * 16;
                unsigned ah[4];
                unsigned off;
                if (A_T) {
                    off = aBase + (ks + la7 + 8 * la_hi4) * 272 + (mf + 8 * la_b3) * 2;
                } else {
                    off = aBase + (mf + la15) * 80 + (ks + 8 * la_hi4) * 2;
                }
                ldsm4<A_T>(ah, off);
                #pragma unroll
                for (int ni = 0; ni < 4; ni++)
                    mma_f16(acc[mi][ni], ah, bh[ni]);
            }
        }
    }

    // ---- epilogue ----
    #pragma unroll
    for (int mi = 0; mi < 4; mi++) {
        #pragma unroll
        for (int half = 0; half < 2; half++) {
            const int row = m0 + wm + mi * 16 + gid + half * 8;
            const float bv = (OUTM == 1 || OUTM == 2) ? bias[row] : 0.f;
            #pragma unroll
            for (int ni = 0; ni < 4; ni++) {
                const int col = n0 + wn + ni * 8 + tid4 * 2;
                float v0 = acc[mi][ni][half * 2 + 0] * alpha + bv;
                float v1 = acc[mi][ni][half * 2 + 1] * alpha + bv;
                const size_t off = (size_t)row * N + col;
                if (OUTM == 0) {
                    *(float2*)&C[off] = make_float2(v0, v1);
                } else if (OUTM == 1) {
                    const float* rp = res + off;
                    *(float2*)&C[off] = make_float2(v0 + rp[0], v1 + rp[1]);
                } else {
                    *(__half2*)&Ch[off] = __floats2half2_rn(v0, v1);
                }
            }
        }
    }
}

// ---------------------------------------------------------------------------
// Row softmax over 1024 elements + fp16 output.
// ---------------------------------------------------------------------------
__global__ void softmax_k(const float* __restrict__ S) {
    const size_t row = blockIdx.x;
    const float4* p = (const float4*)(S + row * (size_t)NPIX);
    float4 v = p[threadIdx.x];

    __shared__ float sh[8];
    __shared__ float bcast;

    float mx = fmaxf(fmaxf(v.x, v.y), fmaxf(v.z, v.w));
    mx = warp_max(mx);
    if (!(threadIdx.x & 31)) sh[threadIdx.x >> 5] = mx;
    __syncthreads();
    if (threadIdx.x < 32) {
        float t = (threadIdx.x < 8) ? sh[threadIdx.x] : -1e30f;
        t = warp_max(t);
        if (!threadIdx.x) bcast = t;
    }
    __syncthreads();
    mx = bcast;
    __syncthreads();

    v.x = __expf(v.x - mx); v.y = __expf(v.y - mx);
    v.z = __expf(v.z - mx); v.w = __expf(v.w - mx);
    float s = v.x + v.y + v.z + v.w;
    s = warp_sum(s);
    if (!(threadIdx.x & 31)) sh[threadIdx.x >> 5] = s;
    __syncthreads();
    if (threadIdx.x < 32) {
        float t = (threadIdx.x < 8) ? sh[threadIdx.x] : 0.f;
        t = warp_sum(t);
        if (!threadIdx.x) bcast = t;
    }
    __syncthreads();
    const float inv = 1.f / bcast;
    const size_t i2 = row * (NPIX / 2) + threadIdx.x * 2;
    ((__half2*)g_attb)[i2 + 0] = __floats2half2_rn(v.x * inv, v.y * inv);
    ((__half2*)g_attb)[i2 + 1] = __floats2half2_rn(v.z * inv, v.w * inv);
}

// ---------------------------------------------------------------------------
// Launch
// ---------------------------------------------------------------------------
extern "C" void kernel_launch(void* const* d_in, const int* in_sizes, int n_in,
                              void* d_out, int out_size) {
    const float* x  = (const float*)d_in[0];
    const float* nw = (const float*)d_in[1];
    const float* nb = (const float*)d_in[2];
    const float* qw = (const float*)d_in[3];
    const float* qb = (const float*)d_in[4];
    const float* pw = (const float*)d_in[5];
    const float* pb = (const float*)d_in[6];
    float* out = (float*)d_out;

    __half *wq, *wp, *hb, *qk, *at, *ho;
    float* attn;
    cudaGetSymbolAddress((void**)&wq, g_wq);
    cudaGetSymbolAddress((void**)&wp, g_wp);
    cudaGetSymbolAddress((void**)&hb, g_hb);
    cudaGetSymbolAddress((void**)&qk, g_qkvb);
    cudaGetSymbolAddress((void**)&at, g_attb);
    cudaGetSymbolAddress((void**)&ho, g_houtb);
    cudaGetSymbolAddress((void**)&attn, g_attn);

    const size_t sH   = (size_t)CH * NPIX;
    const size_t sQKV = (size_t)3 * CH * NPIX;
    const size_t sAT  = (size_t)NPIX * NPIX;

    // 4-stage dynamic smem: A tile (A_T? 8704:10240) + B tile (same formula)
    const int SM_QKV = 4 * (10240 + 8704);   // 75776  (A=false, B_T=true)
    const int SM_SC  = 4 * (8704 + 8704);    // 69632  (A_T, B_T)
    const int SM_AV  = 4 * (10240 + 10240);  // 81920  (A=false, B=false)
    const int SM_PR  = SM_QKV;

    cudaFuncSetAttribute(gemm_h<false,true ,2>, cudaFuncAttributeMaxDynamicSharedMemorySize, SM_QKV);
    cudaFuncSetAttribute(gemm_h<true ,true ,0>, cudaFuncAttributeMaxDynamicSharedMemorySize, SM_SC);
    cudaFuncSetAttribute(gemm_h<false,false,3>, cudaFuncAttributeMaxDynamicSharedMemorySize, SM_AV);
    cudaFuncSetAttribute(gemm_h<false,true ,1>, cudaFuncAttributeMaxDynamicSharedMemorySize, SM_PR);

    // 0) round weights to fp16
    wround_k<<<(3*CH*CH)/(4*256), 256>>>(qw, wq);
    wround_k<<<(CH*CH)/(4*256), 256>>>(pw, wp);

    // 1) fused GroupNorm (fp16 h)
    gn_fused_k<<<BATCH * NGRP, 256>>>(x, nw, nb);

    // 2) QKV = qkv_w @ h + qkv_b  (M=1536,N=1024,K=512)  A:[M][K], B:[K][N]
    gemm_h<false,true,2><<<dim3(8,12,BATCH), 256, SM_QKV>>>(
        wq, hb, nullptr, qk, qb, nullptr,
        3*CH, NPIX, CH, CH, NPIX, 0, sH, sQKV, 1.f);

    // 3) scores[n][m] = scale * sum_c q[c][n] k[c][m]  (M=N=1024,K=512)
    const float scale = 0.044194173824159216f;
    gemm_h<true,true,0><<<dim3(8,8,BATCH), 256, SM_SC>>>(
        qk, qk + sH, attn, nullptr, nullptr, nullptr,
        NPIX, NPIX, CH, NPIX, NPIX, sQKV, sQKV, sAT, scale);

    // 4) softmax rows (fp16 out)
    softmax_k<<<BATCH * NPIX, 256>>>(attn);

    // 5) hout[c][n] = sum_m v[c][m] attn[n][m]  (M=512,N=1024,K=1024)
    gemm_h<false,false,3><<<dim3(8,4,BATCH), 256, SM_AV>>>(
        qk + 2*sH, at, nullptr, ho, nullptr, nullptr,
        CH, NPIX, NPIX, NPIX, NPIX, sQKV, sAT, sH, 1.f);

    // 6) out = x + proj_w @ hout + proj_b  (M=512,N=1024,K=512)
    gemm_h<false,true,1><<<dim3(8,4,BATCH), 256, SM_PR>>>(
        wp, ho, out, nullptr, pb, x,
        CH, NPIX, CH, CH, NPIX, 0, sH, sH, 1.f);
}